// round 2
// baseline (speedup 1.0000x reference)
#include <cuda_runtime.h>
#include <cstdint>
#include <cstddef>

// ---------------------------------------------------------------------------
// Problem: out = (relu(x @ qdq(w_fc).T)^2) @ qdq(w_proj).T
//   x      [4,2048,2048] fp32  -> flatten M=8192, K1=2048
//   w_fc   [8192,2048]         -> N1=8192
//   w_proj [2048,8192]         -> N2=2048, K2=8192
// qdq = per-64-block (along input dim) symmetric int5 with MSE scale search
// over 16 shrink factors.
// Plan: quant kernels -> tf32-round x -> tf32 mma.sync GEMM1 (+relu^2 epi,
// tf32-rounded) -> tf32 mma.sync GEMM2.
// ---------------------------------------------------------------------------

#define BM 128
#define BN 128
#define BK 32
#define SLD (BK + 4)       // padded smem row stride (floats): conflict-free frags
#define GTHREADS 256

// Scratch (allocation-free: __device__ globals)
__device__ float g_xr[8192ull * 2048];      // tf32-rounded x
__device__ float g_wfc[8192ull * 2048];     // qdq(w_fc), tf32-rounded
__device__ float g_wproj[2048ull * 8192];   // qdq(w_proj), tf32-rounded
__device__ float g_h2[8192ull * 8192];      // relu(h)^2, tf32-rounded

// ---------------------------------------------------------------------------

__device__ __forceinline__ float tf32r(float x) {
    uint32_t u;
    asm("cvt.rna.tf32.f32 %0, %1;" : "=r"(u) : "f"(x));
    return __uint_as_float(u);
}

__device__ __forceinline__ void cp16(float* s, const float* g) {
    uint32_t sa = (uint32_t)__cvta_generic_to_shared(s);
    asm volatile("cp.async.cg.shared.global [%0], [%1], 16;\n" :: "r"(sa), "l"(g));
}
__device__ __forceinline__ void cp_commit() { asm volatile("cp.async.commit_group;\n"); }
template <int N>
__device__ __forceinline__ void cp_wait() { asm volatile("cp.async.wait_group %0;\n" :: "n"(N)); }

__device__ __forceinline__ void mma8(float c[4], const uint32_t a[4], const uint32_t b[2]) {
    asm volatile(
        "mma.sync.aligned.m16n8k8.row.col.f32.tf32.tf32.f32 "
        "{%0,%1,%2,%3}, {%4,%5,%6,%7}, {%8,%9}, {%0,%1,%2,%3};\n"
        : "+f"(c[0]), "+f"(c[1]), "+f"(c[2]), "+f"(c[3])
        : "r"(a[0]), "r"(a[1]), "r"(a[2]), "r"(a[3]), "r"(b[0]), "r"(b[1]));
}

// ---------------------------------------------------------------------------
// Quantize-dequantize: one warp per 64-element block (contiguous along I).
// Matches reference: base = max(amax,1e-8)/15; scan 16 shrinks; strict '<'.
// Output stored tf32-rounded (GEMM consumes tf32 anyway).
// ---------------------------------------------------------------------------
__global__ void quant_kernel(const float* __restrict__ w, float* __restrict__ wq,
                             int nblocks) {
    int b = blockIdx.x * 8 + (threadIdx.x >> 5);
    int lane = threadIdx.x & 31;
    if (b >= nblocks) return;
    const float* p = w + (size_t)b * 64;
    float w0 = p[lane];
    float w1 = p[lane + 32];

    float amax = fmaxf(fabsf(w0), fabsf(w1));
    #pragma unroll
    for (int o = 16; o; o >>= 1) amax = fmaxf(amax, __shfl_xor_sync(0xffffffffu, amax, o));

    float base = __fdiv_rn(fmaxf(amax, 1e-8f), 15.0f);
    const float shr[16] = {0.4f, 0.44f, 0.48f, 0.52f, 0.56f, 0.6f, 0.64f, 0.68f,
                           0.72f, 0.76f, 0.8f, 0.84f, 0.88f, 0.92f, 0.96f, 1.0f};
    float best_err = __int_as_float(0x7f800000);  // +inf
    float best_scale = base;
    #pragma unroll
    for (int i = 0; i < 16; i++) {
        float s = base * shr[i];
        float q0 = fminf(fmaxf(rintf(__fdiv_rn(w0, s)), -15.f), 15.f);
        float q1 = fminf(fmaxf(rintf(__fdiv_rn(w1, s)), -15.f), 15.f);
        float d0 = q0 * s - w0;
        float d1 = q1 * s - w1;
        float e = d0 * d0 + d1 * d1;
        #pragma unroll
        for (int o = 16; o; o >>= 1) e += __shfl_xor_sync(0xffffffffu, e, o);
        if (e < best_err) { best_err = e; best_scale = s; }
    }
    float q0 = fminf(fmaxf(rintf(__fdiv_rn(w0, best_scale)), -15.f), 15.f);
    float q1 = fminf(fmaxf(rintf(__fdiv_rn(w1, best_scale)), -15.f), 15.f);
    wq[(size_t)b * 64 + lane]      = tf32r(q0 * best_scale);
    wq[(size_t)b * 64 + lane + 32] = tf32r(q1 * best_scale);
}

// tf32-round x (vectorized, grid-stride)
__global__ void round_kernel(const float* __restrict__ in, float* __restrict__ out, int n4) {
    int i = blockIdx.x * blockDim.x + threadIdx.x;
    int stride = gridDim.x * blockDim.x;
    for (; i < n4; i += stride) {
        float4 v = reinterpret_cast<const float4*>(in)[i];
        v.x = tf32r(v.x); v.y = tf32r(v.y); v.z = tf32r(v.z); v.w = tf32r(v.w);
        reinterpret_cast<float4*>(out)[i] = v;
    }
}

// ---------------------------------------------------------------------------
// TN GEMM: C[M,N] = A[M,K] @ B[N,K]^T   (A,B pre-rounded to tf32)
// 128x128 block tile, BK=32, 8 warps in 2x4 -> 64x32 warp tile, m16n8k8 tf32.
// RELUSQ: C := tf32(relu(acc)^2) (feeds GEMM2); else plain store.
// ---------------------------------------------------------------------------
template <bool RELUSQ>
__global__ __launch_bounds__(GTHREADS, 2)
void gemm_tn(const float* __restrict__ A, const float* __restrict__ B,
             float* __restrict__ C, int M, int N, int K) {
    extern __shared__ float smem[];
    float* As = smem;                       // 2 * BM * SLD
    float* Bs = smem + 2 * BM * SLD;        // 2 * BN * SLD

    const int t = threadIdx.x;
    const int bm = blockIdx.y;
    const int bn = blockIdx.x;
    const int lane = t & 31;
    const int warp = t >> 5;
    const int wm = warp >> 2;               // 0..1
    const int wn = warp & 3;                // 0..3
    const int g = lane >> 2;                // 0..7
    const int tg = lane & 3;                // 0..3

    const int KT = K / BK;

    // tile loader: 128 rows x 32 cols fp32 = 1024 float4 -> 4 per thread
    auto load_tile = [&](int buf, int kt) {
        const float* Ag = A + (size_t)(bm * BM) * K + kt * BK;
        const float* Bg = B + (size_t)(bn * BN) * K + kt * BK;
        float* Ad = As + buf * BM * SLD;
        float* Bd = Bs + buf * BN * SLD;
        #pragma unroll
        for (int i = 0; i < 4; i++) {
            int s = t + i * GTHREADS;
            int row = s >> 3;
            int c4 = (s & 7) << 2;
            cp16(Ad + row * SLD + c4, Ag + (size_t)row * K + c4);
        }
        #pragma unroll
        for (int i = 0; i < 4; i++) {
            int s = t + i * GTHREADS;
            int row = s >> 3;
            int c4 = (s & 7) << 2;
            cp16(Bd + row * SLD + c4, Bg + (size_t)row * K + c4);
        }
    };

    float c[4][4][4];
    #pragma unroll
    for (int mi = 0; mi < 4; mi++)
        #pragma unroll
        for (int ni = 0; ni < 4; ni++)
            #pragma unroll
            for (int r = 0; r < 4; r++) c[mi][ni][r] = 0.f;

    load_tile(0, 0);
    cp_commit();

    for (int kt = 0; kt < KT; kt++) {
        int cur = kt & 1;
        if (kt + 1 < KT) {
            load_tile(cur ^ 1, kt + 1);
            cp_commit();
            cp_wait<1>();
        } else {
            cp_wait<0>();
        }
        __syncthreads();

        const float* Ab = As + cur * BM * SLD + (wm * 64) * SLD;
        const float* Bb = Bs + cur * BN * SLD + (wn * 32) * SLD;

        #pragma unroll
        for (int kk = 0; kk < 4; kk++) {
            const int k0 = kk * 8;
            uint32_t a[4][4], b[4][2];
            #pragma unroll
            for (int mi = 0; mi < 4; mi++) {
                const float* r0 = Ab + (mi * 16 + g) * SLD + k0 + tg;
                a[mi][0] = __float_as_uint(r0[0]);
                a[mi][2] = __float_as_uint(r0[4]);
                const float* r1 = r0 + 8 * SLD;
                a[mi][1] = __float_as_uint(r1[0]);
                a[mi][3] = __float_as_uint(r1[4]);
            }
            #pragma unroll
            for (int ni = 0; ni < 4; ni++) {
                const float* rb = Bb + (ni * 8 + g) * SLD + k0 + tg;
                b[ni][0] = __float_as_uint(rb[0]);
                b[ni][1] = __float_as_uint(rb[4]);
            }
            #pragma unroll
            for (int mi = 0; mi < 4; mi++)
                #pragma unroll
                for (int ni = 0; ni < 4; ni++)
                    mma8(c[mi][ni], a[mi], b[ni]);
        }
        __syncthreads();
    }

    // epilogue
    const int row0 = bm * BM + wm * 64;
    const int col0 = bn * BN + wn * 32;
    #pragma unroll
    for (int mi = 0; mi < 4; mi++) {
        #pragma unroll
        for (int ni = 0; ni < 4; ni++) {
            float v0 = c[mi][ni][0], v1 = c[mi][ni][1];
            float v2 = c[mi][ni][2], v3 = c[mi][ni][3];
            if (RELUSQ) {
                v0 = fmaxf(v0, 0.f); v0 = tf32r(v0 * v0);
                v1 = fmaxf(v1, 0.f); v1 = tf32r(v1 * v1);
                v2 = fmaxf(v2, 0.f); v2 = tf32r(v2 * v2);
                v3 = fmaxf(v3, 0.f); v3 = tf32r(v3 * v3);
            }
            int r = row0 + mi * 16 + g;
            int cc = col0 + ni * 8 + (tg << 1);
            *reinterpret_cast<float2*>(C + (size_t)r * N + cc)       = make_float2(v0, v1);
            *reinterpret_cast<float2*>(C + (size_t)(r + 8) * N + cc) = make_float2(v2, v3);
        }
    }
}

// ---------------------------------------------------------------------------

extern "C" void kernel_launch(void* const* d_in, const int* in_sizes, int n_in,
                              void* d_out, int out_size) {
    const float* x     = (const float*)d_in[0];   // [8192, 2048]
    const float* wfc   = (const float*)d_in[1];   // [8192, 2048]
    const float* wproj = (const float*)d_in[2];   // [2048, 8192]
    float* out = (float*)d_out;                    // [8192, 2048]

    float *xr, *wfcq, *wprojq, *h2;
    cudaGetSymbolAddress((void**)&xr, g_xr);
    cudaGetSymbolAddress((void**)&wfcq, g_wfc);
    cudaGetSymbolAddress((void**)&wprojq, g_wproj);
    cudaGetSymbolAddress((void**)&h2, g_h2);

    const int M = 8192, K1 = 2048, N1 = 8192, K2 = 8192, N2 = 2048;

    const int smem_bytes = (2 * BM * SLD + 2 * BN * SLD) * (int)sizeof(float);  // 73728
    cudaFuncSetAttribute(gemm_tn<true>,  cudaFuncAttributeMaxDynamicSharedMemorySize, smem_bytes);
    cudaFuncSetAttribute(gemm_tn<false>, cudaFuncAttributeMaxDynamicSharedMemorySize, smem_bytes);

    // 1. quantize-dequantize both weights (warp per 64-block, 8 blocks/CTA)
    {
        int nb_fc = (N1 * K1) / 64;     // 262144
        quant_kernel<<<nb_fc / 8, 256>>>(wfc, wfcq, nb_fc);
        int nb_pj = (N2 * K2) / 64;     // 262144
        quant_kernel<<<nb_pj / 8, 256>>>(wproj, wprojq, nb_pj);
    }

    // 2. tf32-round x
    {
        int n4 = (M * K1) / 4;          // 4,194,304
        round_kernel<<<2048, 256>>>(x, xr, n4);
    }

    // 3. h2 = tf32(relu(x @ wfcq^T)^2)
    {
        dim3 grid(N1 / BN, M / BM);     // (64, 64)
        gemm_tn<true><<<grid, GTHREADS, smem_bytes>>>(xr, wfcq, h2, M, N1, K1);
    }

    // 4. out = h2 @ wprojq^T
    {
        dim3 grid(N2 / BN, M / BM);     // (16, 64)
        gemm_tn<false><<<grid, GTHREADS, smem_bytes>>>(h2, wprojq, out, M, N2, K2);
    }
}

// round 4
// speedup vs baseline: 1.8030x; 1.8030x over previous
#include <cuda_runtime.h>
#include <cuda_fp16.h>
#include <cstdint>
#include <cstddef>

// ---------------------------------------------------------------------------
// out = (relu(x @ qdq(w_fc)^T)^2) @ qdq(w_proj)^T
// M=8192, K1=2048, N1=8192 ; K2=8192, N2=2048
// Round 4: fp16 mma.sync.m16n8k16 (fp32 accum) — same 10-bit mantissa as tf32,
// 2x the legacy tensor rate. ldmatrix.x4 fragment loads from XOR-swizzled smem,
// 3-stage cp.async pipeline, 128x128 CTA tile / 64x32 warp tile.
// (tcgen05 is rejected by this bench's sm_100 ptxas target — verified R3.)
// ---------------------------------------------------------------------------

#define BM 128
#define BN 128
#define BKH 64                    // halves per k-tile (128 B rows)
#define STAGES 3
#define STAGE_A (BM * 128)        // bytes
#define STAGE_B (BN * 128)
#define STAGE_BYTES (STAGE_A + STAGE_B)          // 32768
#define SMEM_TOTAL (STAGES * STAGE_BYTES)        // 98304

// Scratch (allocation-free, 16B-aligned for cp.async)
__device__ __align__(256) __half g_xh[8192ull * 2048];
__device__ __align__(256) __half g_wfc[8192ull * 2048];
__device__ __align__(256) __half g_wpj[2048ull * 8192];
__device__ __align__(256) __half g_h2[8192ull * 8192];

// ---------------------------------------------------------------------------
__device__ __forceinline__ void cp16(uint32_t s, const void* g) {
    asm volatile("cp.async.cg.shared.global [%0], [%1], 16;" :: "r"(s), "l"(g));
}
__device__ __forceinline__ void cp_commit() { asm volatile("cp.async.commit_group;"); }
template <int N>
__device__ __forceinline__ void cp_wait() { asm volatile("cp.async.wait_group %0;" :: "n"(N)); }

__device__ __forceinline__ void ldsm4(uint32_t& r0, uint32_t& r1, uint32_t& r2,
                                      uint32_t& r3, uint32_t addr) {
    asm volatile("ldmatrix.sync.aligned.m8n8.x4.shared.b16 {%0,%1,%2,%3}, [%4];"
                 : "=r"(r0), "=r"(r1), "=r"(r2), "=r"(r3) : "r"(addr));
}

__device__ __forceinline__ void mma16(float c[4], const uint32_t a[4], const uint32_t b[2]) {
    asm volatile(
        "mma.sync.aligned.m16n8k16.row.col.f32.f16.f16.f32 "
        "{%0,%1,%2,%3}, {%4,%5,%6,%7}, {%8,%9}, {%0,%1,%2,%3};"
        : "+f"(c[0]), "+f"(c[1]), "+f"(c[2]), "+f"(c[3])
        : "r"(a[0]), "r"(a[1]), "r"(a[2]), "r"(a[3]), "r"(b[0]), "r"(b[1]));
}

// ---------------------------------------------------------------------------
// Quantize-dequantize (math identical to verified R2), output fp16.
// ---------------------------------------------------------------------------
__global__ void quant_kernel(const float* __restrict__ w, __half* __restrict__ wq,
                             int nblocks) {
    int b = blockIdx.x * 8 + (threadIdx.x >> 5);
    int lane = threadIdx.x & 31;
    if (b >= nblocks) return;
    const float* p = w + (size_t)b * 64;
    float w0 = p[lane];
    float w1 = p[lane + 32];

    float amax = fmaxf(fabsf(w0), fabsf(w1));
    #pragma unroll
    for (int o = 16; o; o >>= 1) amax = fmaxf(amax, __shfl_xor_sync(0xffffffffu, amax, o));

    float base = __fdiv_rn(fmaxf(amax, 1e-8f), 15.0f);
    const float shr[16] = {0.4f, 0.44f, 0.48f, 0.52f, 0.56f, 0.6f, 0.64f, 0.68f,
                           0.72f, 0.76f, 0.8f, 0.84f, 0.88f, 0.92f, 0.96f, 1.0f};
    float best_err = __int_as_float(0x7f800000);
    float best_scale = base;
    #pragma unroll
    for (int i = 0; i < 16; i++) {
        float s = base * shr[i];
        float q0 = fminf(fmaxf(rintf(__fdiv_rn(w0, s)), -15.f), 15.f);
        float q1 = fminf(fmaxf(rintf(__fdiv_rn(w1, s)), -15.f), 15.f);
        float d0 = q0 * s - w0;
        float d1 = q1 * s - w1;
        float e = d0 * d0 + d1 * d1;
        #pragma unroll
        for (int o = 16; o; o >>= 1) e += __shfl_xor_sync(0xffffffffu, e, o);
        if (e < best_err) { best_err = e; best_scale = s; }
    }
    float q0 = fminf(fmaxf(rintf(__fdiv_rn(w0, best_scale)), -15.f), 15.f);
    float q1 = fminf(fmaxf(rintf(__fdiv_rn(w1, best_scale)), -15.f), 15.f);
    wq[(size_t)b * 64 + lane]      = __float2half_rn(q0 * best_scale);
    wq[(size_t)b * 64 + lane + 32] = __float2half_rn(q1 * best_scale);
}

// fp32 -> fp16 convert (vectorized, grid-stride)
__global__ void half_kernel(const float* __restrict__ in, __half* __restrict__ out, int n4) {
    int i = blockIdx.x * blockDim.x + threadIdx.x;
    int stride = gridDim.x * blockDim.x;
    for (; i < n4; i += stride) {
        float4 v = reinterpret_cast<const float4*>(in)[i];
        __half2 h0 = __floats2half2_rn(v.x, v.y);
        __half2 h1 = __floats2half2_rn(v.z, v.w);
        uint2 pk;
        pk.x = *reinterpret_cast<uint32_t*>(&h0);
        pk.y = *reinterpret_cast<uint32_t*>(&h1);
        reinterpret_cast<uint2*>(out)[i] = pk;
    }
}

// ---------------------------------------------------------------------------
// TN GEMM: C[M,N] = A[M,K] @ B[N,K]^T, fp16 in, fp32 accum.
// RELUSQ: C is __half*, stores half(relu(acc)^2); else float*.
// Smem layout per tile: 128 rows x 128B (64 halves), 16B chunk swizzle:
//   phys_chunk = chunk ^ (row & 7)
// ---------------------------------------------------------------------------
template <bool RELUSQ>
__global__ __launch_bounds__(256, 2)
void gemm_h(const __half* __restrict__ A, const __half* __restrict__ B,
            void* __restrict__ Cv, int M, int N_, int K) {
    extern __shared__ char smem[];
    const uint32_t sb = (uint32_t)__cvta_generic_to_shared(smem);

    const int tid = threadIdx.x;
    const int lane = tid & 31;
    const int warp = tid >> 5;
    const int wm = warp >> 2;        // 0..1
    const int wn = warp & 3;         // 0..3
    const int bm = blockIdx.y;
    const int bn = blockIdx.x;

    const __half* Ag = A + (size_t)bm * BM * K;
    const __half* Bg = B + (size_t)bn * BN * K;

    // ---- loader geometry: 1024 chunks (16B) per tile, 4 per thread ----
    const int lrow = tid >> 3;               // 0..31 (+32*i)
    const int lc = tid & 7;                  // chunk col
    const uint32_t lswz = (uint32_t)((lc ^ (lrow & 7)) << 4);   // constant: (lrow+32i)&7 == lrow&7
    const __half* AgT = Ag + (size_t)lrow * K + lc * 8;
    const __half* BgT = Bg + (size_t)lrow * K + lc * 8;

    auto load_stage = [&](int s, int kt) {
        uint32_t as = sb + s * STAGE_BYTES + lrow * 128 + lswz;
        uint32_t bs = as + STAGE_A;
        const __half* ag = AgT + kt * BKH;
        const __half* bg = BgT + kt * BKH;
        #pragma unroll
        for (int i = 0; i < 4; i++)
            cp16(as + i * (32 * 128), ag + (size_t)(32 * i) * K);
        #pragma unroll
        for (int i = 0; i < 4; i++)
            cp16(bs + i * (32 * 128), bg + (size_t)(32 * i) * K);
    };

    // ---- ldmatrix per-lane geometry ----
    const int trow = lane & 7;
    const int tile = lane >> 3;
    const int t01 = tile & 1;
    const int t2 = tile >> 1;
    // base byte offsets within a stage (add stage base + mi/nb offsets + swz(kk))
    const uint32_t Aboff = (uint32_t)((wm * 64 + t01 * 8 + trow) * 128);
    const uint32_t Bboff = (uint32_t)(STAGE_A + (wn * 32 + t01 * 8 + trow) * 128);

    float c[4][4][4];
    #pragma unroll
    for (int mi = 0; mi < 4; mi++)
        #pragma unroll
        for (int ni = 0; ni < 4; ni++)
            #pragma unroll
            for (int r = 0; r < 4; r++) c[mi][ni][r] = 0.f;

    const int KT = K / BKH;

    load_stage(0, 0); cp_commit();
    load_stage(1, 1); cp_commit();

    for (int kt = 0; kt < KT; kt++) {
        if (kt + 2 < KT) load_stage((kt + 2) % 3, kt + 2);
        cp_commit();
        cp_wait<2>();
        __syncthreads();

        const uint32_t stg = sb + (kt % 3) * STAGE_BYTES;
        #pragma unroll
        for (int kk = 0; kk < 4; kk++) {
            const uint32_t swz = (uint32_t)((((2 * kk + t2) ^ trow)) << 4);
            uint32_t a[4][4];
            #pragma unroll
            for (int mi = 0; mi < 4; mi++)
                ldsm4(a[mi][0], a[mi][1], a[mi][2], a[mi][3],
                      stg + Aboff + mi * 2048 + swz);
            uint32_t bf[4][2];
            #pragma unroll
            for (int nb = 0; nb < 2; nb++) {
                uint32_t r0, r1, r2, r3;
                ldsm4(r0, r1, r2, r3, stg + Bboff + nb * 2048 + swz);
                bf[2 * nb][0] = r0; bf[2 * nb][1] = r2;
                bf[2 * nb + 1][0] = r1; bf[2 * nb + 1][1] = r3;
            }
            #pragma unroll
            for (int mi = 0; mi < 4; mi++)
                #pragma unroll
                for (int ni = 0; ni < 4; ni++)
                    mma16(c[mi][ni], a[mi], bf[ni]);
        }
        __syncthreads();
    }

    // ---- epilogue ----
    const int g = lane >> 2;
    const int q = lane & 3;
    const int row0 = bm * BM + wm * 64 + g;
    const int col0 = bn * BN + wn * 32 + q * 2;

    if (RELUSQ) {
        __half* C = (__half*)Cv;
        #pragma unroll
        for (int mi = 0; mi < 4; mi++) {
            #pragma unroll
            for (int ni = 0; ni < 4; ni++) {
                float v0 = fmaxf(c[mi][ni][0], 0.f); v0 *= v0;
                float v1 = fmaxf(c[mi][ni][1], 0.f); v1 *= v1;
                float v2 = fmaxf(c[mi][ni][2], 0.f); v2 *= v2;
                float v3 = fmaxf(c[mi][ni][3], 0.f); v3 *= v3;
                int r = row0 + mi * 16;
                int cc = col0 + ni * 8;
                __half2 h01 = __floats2half2_rn(v0, v1);
                __half2 h23 = __floats2half2_rn(v2, v3);
                *reinterpret_cast<__half2*>(C + (size_t)r * N_ + cc) = h01;
                *reinterpret_cast<__half2*>(C + (size_t)(r + 8) * N_ + cc) = h23;
            }
        }
    } else {
        float* C = (float*)Cv;
        #pragma unroll
        for (int mi = 0; mi < 4; mi++) {
            #pragma unroll
            for (int ni = 0; ni < 4; ni++) {
                int r = row0 + mi * 16;
                int cc = col0 + ni * 8;
                *reinterpret_cast<float2*>(C + (size_t)r * N_ + cc) =
                    make_float2(c[mi][ni][0], c[mi][ni][1]);
                *reinterpret_cast<float2*>(C + (size_t)(r + 8) * N_ + cc) =
                    make_float2(c[mi][ni][2], c[mi][ni][3]);
            }
        }
    }
}

// ---------------------------------------------------------------------------

extern "C" void kernel_launch(void* const* d_in, const int* in_sizes, int n_in,
                              void* d_out, int out_size) {
    const float* x     = (const float*)d_in[0];   // [8192, 2048]
    const float* wfc   = (const float*)d_in[1];   // [8192, 2048]
    const float* wproj = (const float*)d_in[2];   // [2048, 8192]
    float* out = (float*)d_out;                    // [8192, 2048]

    __half *xh, *wfcq, *wpjq, *h2;
    cudaGetSymbolAddress((void**)&xh, g_xh);
    cudaGetSymbolAddress((void**)&wfcq, g_wfc);
    cudaGetSymbolAddress((void**)&wpjq, g_wpj);
    cudaGetSymbolAddress((void**)&h2, g_h2);

    const int M = 8192, K1 = 2048, N1 = 8192, K2 = 8192, N2 = 2048;

    cudaFuncSetAttribute(gemm_h<true>,  cudaFuncAttributeMaxDynamicSharedMemorySize, SMEM_TOTAL);
    cudaFuncSetAttribute(gemm_h<false>, cudaFuncAttributeMaxDynamicSharedMemorySize, SMEM_TOTAL);

    // 1. quantize-dequantize weights -> fp16
    {
        int nb_fc = (N1 * K1) / 64;
        quant_kernel<<<nb_fc / 8, 256>>>(wfc, wfcq, nb_fc);
        int nb_pj = (N2 * K2) / 64;
        quant_kernel<<<nb_pj / 8, 256>>>(wproj, wpjq, nb_pj);
    }

    // 2. x -> fp16
    half_kernel<<<2048, 256>>>(x, xh, (M * K1) / 4);

    // 3. h2 = half(relu(x @ wfcq^T)^2)
    {
        dim3 grid(N1 / BN, M / BM);   // (64, 64)
        gemm_h<true><<<grid, 256, SMEM_TOTAL>>>(xh, wfcq, (void*)h2, M, N1, K1);
    }

    // 4. out = h2 @ wpjq^T   (fp32 out)
    {
        dim3 grid(N2 / BN, M / BM);   // (16, 64)
        gemm_h<false><<<grid, 256, SMEM_TOTAL>>>(h2, wpjq, (void*)out, M, N2, K2);
    }
}

// round 5
// speedup vs baseline: 2.0051x; 1.1121x over previous
#include <cuda_runtime.h>
#include <cuda_fp16.h>
#include <cstdint>
#include <cstddef>

// ---------------------------------------------------------------------------
// out = (relu(x @ qdq(w_fc)^T)^2) @ qdq(w_proj)^T
// M=8192, K1=2048, N1=8192 ; K2=8192, N2=2048
// Round 5: fp16 m16n8k16 HMMA. 64x64 warp tiles (4 warps / 128 threads per
// 128x128 CTA tile, 2 CTAs/SM), single __syncthreads per k-tile, quant kernel
// with one division per block (reciprocal-multiply scale search).
// ---------------------------------------------------------------------------

#define BM 128
#define BN 128
#define BKH 64                    // halves per k-tile (128 B rows)
#define STAGES 3
#define STAGE_A (BM * 128)        // bytes
#define STAGE_B (BN * 128)
#define STAGE_BYTES (STAGE_A + STAGE_B)          // 32768
#define SMEM_TOTAL (STAGES * STAGE_BYTES)        // 98304

// Scratch (allocation-free, aligned for cp.async)
__device__ __align__(256) __half g_xh[8192ull * 2048];
__device__ __align__(256) __half g_wfc[8192ull * 2048];
__device__ __align__(256) __half g_wpj[2048ull * 8192];
__device__ __align__(256) __half g_h2[8192ull * 8192];

// ---------------------------------------------------------------------------
__device__ __forceinline__ void cp16(uint32_t s, const void* g) {
    asm volatile("cp.async.cg.shared.global [%0], [%1], 16;" :: "r"(s), "l"(g));
}
__device__ __forceinline__ void cp_commit() { asm volatile("cp.async.commit_group;"); }
template <int N>
__device__ __forceinline__ void cp_wait() { asm volatile("cp.async.wait_group %0;" :: "n"(N)); }

__device__ __forceinline__ void ldsm4(uint32_t& r0, uint32_t& r1, uint32_t& r2,
                                      uint32_t& r3, uint32_t addr) {
    asm volatile("ldmatrix.sync.aligned.m8n8.x4.shared.b16 {%0,%1,%2,%3}, [%4];"
                 : "=r"(r0), "=r"(r1), "=r"(r2), "=r"(r3) : "r"(addr));
}

__device__ __forceinline__ void mma16(float c[4], const uint32_t a[4], const uint32_t b[2]) {
    asm volatile(
        "mma.sync.aligned.m16n8k16.row.col.f32.f16.f16.f32 "
        "{%0,%1,%2,%3}, {%4,%5,%6,%7}, {%8,%9}, {%0,%1,%2,%3};"
        : "+f"(c[0]), "+f"(c[1]), "+f"(c[2]), "+f"(c[3])
        : "r"(a[0]), "r"(a[1]), "r"(a[2]), "r"(a[3]), "r"(b[0]), "r"(b[1]));
}

// ---------------------------------------------------------------------------
// Quantize-dequantize: warp per 64-block; ONE division per block, shrink
// search via reciprocal multiplies. Output fp16.
// ---------------------------------------------------------------------------
__global__ __launch_bounds__(256)
void quant_kernel(const float* __restrict__ w, __half* __restrict__ wq,
                  int nblocks) {
    int b = blockIdx.x * 8 + (threadIdx.x >> 5);
    int lane = threadIdx.x & 31;
    if (b >= nblocks) return;
    const float* p = w + (size_t)b * 64;
    float w0 = p[lane];
    float w1 = p[lane + 32];

    float amax = fmaxf(fabsf(w0), fabsf(w1));
    #pragma unroll
    for (int o = 16; o; o >>= 1) amax = fmaxf(amax, __shfl_xor_sync(0xffffffffu, amax, o));

    float am = fmaxf(amax, 1e-8f);
    float base = am * (1.0f / 15.0f) * 1.0f;          // base scale (mul ok: /15 exactly? use div)
    base = __fdiv_rn(am, 15.0f);
    float invb = __fdiv_rn(15.0f, am);

    const float shr[16] = {0.4f, 0.44f, 0.48f, 0.52f, 0.56f, 0.6f, 0.64f, 0.68f,
                           0.72f, 0.76f, 0.8f, 0.84f, 0.88f, 0.92f, 0.96f, 1.0f};
    const float ishr[16] = {2.5f, 1.0f/0.44f, 1.0f/0.48f, 1.0f/0.52f,
                            1.0f/0.56f, 1.0f/0.6f, 1.0f/0.64f, 1.0f/0.68f,
                            1.0f/0.72f, 1.0f/0.76f, 1.25f, 1.0f/0.84f,
                            1.0f/0.88f, 1.0f/0.92f, 1.0f/0.96f, 1.0f};
    float best_err = __int_as_float(0x7f800000);
    float best_scale = base;
    float best_inv = invb;
    #pragma unroll
    for (int i = 0; i < 16; i++) {
        float s = base * shr[i];
        float inv = invb * ishr[i];
        float q0 = fminf(fmaxf(rintf(w0 * inv), -15.f), 15.f);
        float q1 = fminf(fmaxf(rintf(w1 * inv), -15.f), 15.f);
        float d0 = fmaf(q0, s, -w0);
        float d1 = fmaf(q1, s, -w1);
        float e = fmaf(d0, d0, d1 * d1);
        #pragma unroll
        for (int o = 16; o; o >>= 1) e += __shfl_xor_sync(0xffffffffu, e, o);
        if (e < best_err) { best_err = e; best_scale = s; best_inv = inv; }
    }
    float q0 = fminf(fmaxf(rintf(w0 * best_inv), -15.f), 15.f);
    float q1 = fminf(fmaxf(rintf(w1 * best_inv), -15.f), 15.f);
    wq[(size_t)b * 64 + lane]      = __float2half_rn(q0 * best_scale);
    wq[(size_t)b * 64 + lane + 32] = __float2half_rn(q1 * best_scale);
}

// fp32 -> fp16 convert (vectorized, grid-stride)
__global__ void half_kernel(const float* __restrict__ in, __half* __restrict__ out, int n4) {
    int i = blockIdx.x * blockDim.x + threadIdx.x;
    int stride = gridDim.x * blockDim.x;
    for (; i < n4; i += stride) {
        float4 v = reinterpret_cast<const float4*>(in)[i];
        __half2 h0 = __floats2half2_rn(v.x, v.y);
        __half2 h1 = __floats2half2_rn(v.z, v.w);
        uint2 pk;
        pk.x = *reinterpret_cast<uint32_t*>(&h0);
        pk.y = *reinterpret_cast<uint32_t*>(&h1);
        reinterpret_cast<uint2*>(out)[i] = pk;
    }
}

// ---------------------------------------------------------------------------
// TN GEMM: C[M,N] = A[M,K] @ B[N,K]^T, fp16 in, fp32 accum.
// 128 threads, 4 warps in 2x2, 64x64 warp tile. 3-stage cp.async,
// one __syncthreads per k-tile. XOR 16B-chunk swizzle (phys = c ^ (row&7)).
// ---------------------------------------------------------------------------
template <bool RELUSQ>
__global__ __launch_bounds__(128, 2)
void gemm_h(const __half* __restrict__ A, const __half* __restrict__ B,
            void* __restrict__ Cv, int M, int N_, int K) {
    extern __shared__ char smem[];
    const uint32_t sb = (uint32_t)__cvta_generic_to_shared(smem);

    const int tid = threadIdx.x;
    const int lane = tid & 31;
    const int warp = tid >> 5;
    const int wm = warp >> 1;        // 0..1
    const int wn = warp & 1;         // 0..1
    const int bm = blockIdx.y;
    const int bn = blockIdx.x;

    const __half* Ag = A + (size_t)bm * BM * K;
    const __half* Bg = B + (size_t)bn * BN * K;

    // ---- loader: 2048 chunks (16B)/stage, 16 per thread (8 A + 8 B) ----
    const int lrow = tid >> 3;               // 0..15 (+16*i)
    const int lc = tid & 7;
    const uint32_t lswz = (uint32_t)((lc ^ (lrow & 7)) << 4);   // (lrow+16i)&7 == lrow&7
    const __half* AgT = Ag + (size_t)lrow * K + lc * 8;
    const __half* BgT = Bg + (size_t)lrow * K + lc * 8;

    auto load_stage = [&](int s, int kt) {
        uint32_t as = sb + s * STAGE_BYTES + lrow * 128 + lswz;
        uint32_t bs = as + STAGE_A;
        const __half* ag = AgT + kt * BKH;
        const __half* bg = BgT + kt * BKH;
        #pragma unroll
        for (int i = 0; i < 8; i++)
            cp16(as + i * (16 * 128), ag + (size_t)(16 * i) * K);
        #pragma unroll
        for (int i = 0; i < 8; i++)
            cp16(bs + i * (16 * 128), bg + (size_t)(16 * i) * K);
    };

    // ---- ldmatrix per-lane geometry (verified R4 mapping) ----
    const int trow = lane & 7;
    const int tile = lane >> 3;
    const int t01 = tile & 1;
    const int t2 = tile >> 1;
    const uint32_t Aboff = (uint32_t)((wm * 64 + t01 * 8 + trow) * 128);
    const uint32_t Bboff = (uint32_t)(STAGE_A + (wn * 64 + t01 * 8 + trow) * 128);

    float c[4][8][4];
    #pragma unroll
    for (int mi = 0; mi < 4; mi++)
        #pragma unroll
        for (int ni = 0; ni < 8; ni++)
            #pragma unroll
            for (int r = 0; r < 4; r++) c[mi][ni][r] = 0.f;

    const int KT = K / BKH;

    load_stage(0, 0); cp_commit();
    load_stage(1, 1); cp_commit();

    for (int kt = 0; kt < KT; kt++) {
        if (kt == KT - 1) cp_wait<0>(); else cp_wait<1>();
        __syncthreads();
        if (kt + 2 < KT) { load_stage((kt + 2) % 3, kt + 2); cp_commit(); }

        const uint32_t stg = sb + (kt % 3) * STAGE_BYTES;
        #pragma unroll
        for (int kk = 0; kk < 4; kk++) {
            const uint32_t swz = (uint32_t)((((2 * kk + t2) ^ trow)) << 4);
            uint32_t a[4][4];
            #pragma unroll
            for (int mi = 0; mi < 4; mi++)
                ldsm4(a[mi][0], a[mi][1], a[mi][2], a[mi][3],
                      stg + Aboff + mi * 2048 + swz);
            uint32_t bf[8][2];
            #pragma unroll
            for (int nb = 0; nb < 4; nb++) {
                uint32_t r0, r1, r2, r3;
                ldsm4(r0, r1, r2, r3, stg + Bboff + nb * 2048 + swz);
                bf[2 * nb][0] = r0; bf[2 * nb][1] = r2;
                bf[2 * nb + 1][0] = r1; bf[2 * nb + 1][1] = r3;
            }
            #pragma unroll
            for (int mi = 0; mi < 4; mi++)
                #pragma unroll
                for (int ni = 0; ni < 8; ni++)
                    mma16(c[mi][ni], a[mi], bf[ni]);
        }
    }

    // ---- epilogue ----
    const int g = lane >> 2;
    const int q = lane & 3;
    const int row0 = bm * BM + wm * 64 + g;
    const int col0 = bn * BN + wn * 64 + q * 2;

    if (RELUSQ) {
        __half* C = (__half*)Cv;
        #pragma unroll
        for (int mi = 0; mi < 4; mi++) {
            #pragma unroll
            for (int ni = 0; ni < 8; ni++) {
                float v0 = fmaxf(c[mi][ni][0], 0.f); v0 *= v0;
                float v1 = fmaxf(c[mi][ni][1], 0.f); v1 *= v1;
                float v2 = fmaxf(c[mi][ni][2], 0.f); v2 *= v2;
                float v3 = fmaxf(c[mi][ni][3], 0.f); v3 *= v3;
                int r = row0 + mi * 16;
                int cc = col0 + ni * 8;
                *reinterpret_cast<__half2*>(C + (size_t)r * N_ + cc) = __floats2half2_rn(v0, v1);
                *reinterpret_cast<__half2*>(C + (size_t)(r + 8) * N_ + cc) = __floats2half2_rn(v2, v3);
            }
        }
    } else {
        float* C = (float*)Cv;
        #pragma unroll
        for (int mi = 0; mi < 4; mi++) {
            #pragma unroll
            for (int ni = 0; ni < 8; ni++) {
                int r = row0 + mi * 16;
                int cc = col0 + ni * 8;
                *reinterpret_cast<float2*>(C + (size_t)r * N_ + cc) =
                    make_float2(c[mi][ni][0], c[mi][ni][1]);
                *reinterpret_cast<float2*>(C + (size_t)(r + 8) * N_ + cc) =
                    make_float2(c[mi][ni][2], c[mi][ni][3]);
            }
        }
    }
}

// ---------------------------------------------------------------------------

extern "C" void kernel_launch(void* const* d_in, const int* in_sizes, int n_in,
                              void* d_out, int out_size) {
    const float* x     = (const float*)d_in[0];   // [8192, 2048]
    const float* wfc   = (const float*)d_in[1];   // [8192, 2048]
    const float* wproj = (const float*)d_in[2];   // [2048, 8192]
    float* out = (float*)d_out;                    // [8192, 2048]

    __half *xh, *wfcq, *wpjq, *h2;
    cudaGetSymbolAddress((void**)&xh, g_xh);
    cudaGetSymbolAddress((void**)&wfcq, g_wfc);
    cudaGetSymbolAddress((void**)&wpjq, g_wpj);
    cudaGetSymbolAddress((void**)&h2, g_h2);

    const int M = 8192, K1 = 2048, N1 = 8192, K2 = 8192, N2 = 2048;

    cudaFuncSetAttribute(gemm_h<true>,  cudaFuncAttributeMaxDynamicSharedMemorySize, SMEM_TOTAL);
    cudaFuncSetAttribute(gemm_h<false>, cudaFuncAttributeMaxDynamicSharedMemorySize, SMEM_TOTAL);

    // 1. quantize-dequantize weights -> fp16
    {
        int nb_fc = (N1 * K1) / 64;
        quant_kernel<<<nb_fc / 8, 256>>>(wfc, wfcq, nb_fc);
        int nb_pj = (N2 * K2) / 64;
        quant_kernel<<<nb_pj / 8, 256>>>(wproj, wpjq, nb_pj);
    }

    // 2. x -> fp16
    half_kernel<<<2048, 256>>>(x, xh, (M * K1) / 4);

    // 3. h2 = half(relu(x @ wfcq^T)^2)
    {
        dim3 grid(N1 / BN, M / BM);   // (64, 64)
        gemm_h<true><<<grid, 128, SMEM_TOTAL>>>(xh, wfcq, (void*)h2, M, N1, K1);
    }

    // 4. out = h2 @ wpjq^T   (fp32 out)
    {
        dim3 grid(N2 / BN, M / BM);   // (16, 64)
        gemm_h<false><<<grid, 128, SMEM_TOTAL>>>(h2, wpjq, (void*)out, M, N2, K2);
    }
}

// round 7
// speedup vs baseline: 2.1433x; 1.0689x over previous
#include <cuda_runtime.h>
#include <cuda_fp16.h>
#include <cstdint>
#include <cstddef>

// ---------------------------------------------------------------------------
// out = (relu(x @ qdq(w_fc)^T)^2) @ qdq(w_proj)^T
// M=8192, K1=2048, N1=8192 ; K2=8192, N2=2048
// Round 7 (= R6 resubmit after infra failure): fp16 m16n8k16 HMMA, 64x64 warp
// tiles, 3-stage cp.async. K/N as template params (compile-time strides),
// kt-loop unrolled by 3 (compile-time stage bases), explicit fragment
// double-buffering (ldsm kk+1 ahead of mma kk). Targets the 37% tensor-pipe
// idle caused by integer address issue pressure + ldsm latency exposure.
// ---------------------------------------------------------------------------

#define BM 128
#define BN 128
#define BKH 64                    // halves per k-tile (128 B rows)
#define STAGE_A (BM * 128)        // bytes
#define STAGE_B (BN * 128)
#define STAGE_BYTES (STAGE_A + STAGE_B)          // 32768
#define SMEM_TOTAL (3 * STAGE_BYTES)             // 98304

// Scratch (allocation-free)
__device__ __align__(256) __half g_xh[8192ull * 2048];
__device__ __align__(256) __half g_wfc[8192ull * 2048];
__device__ __align__(256) __half g_wpj[2048ull * 8192];
__device__ __align__(256) __half g_h2[8192ull * 8192];

// ---------------------------------------------------------------------------
__device__ __forceinline__ void cp16(uint32_t s, const void* g) {
    asm volatile("cp.async.cg.shared.global [%0], [%1], 16;" :: "r"(s), "l"(g));
}
__device__ __forceinline__ void cp_commit() { asm volatile("cp.async.commit_group;"); }
template <int N>
__device__ __forceinline__ void cp_wait() { asm volatile("cp.async.wait_group %0;" :: "n"(N)); }

__device__ __forceinline__ void ldsm4(uint32_t& r0, uint32_t& r1, uint32_t& r2,
                                      uint32_t& r3, uint32_t addr) {
    asm volatile("ldmatrix.sync.aligned.m8n8.x4.shared.b16 {%0,%1,%2,%3}, [%4];"
                 : "=r"(r0), "=r"(r1), "=r"(r2), "=r"(r3) : "r"(addr));
}

__device__ __forceinline__ void mma16(float c[4], const uint32_t a[4], const uint32_t b[2]) {
    asm volatile(
        "mma.sync.aligned.m16n8k16.row.col.f32.f16.f16.f32 "
        "{%0,%1,%2,%3}, {%4,%5,%6,%7}, {%8,%9}, {%0,%1,%2,%3};"
        : "+f"(c[0]), "+f"(c[1]), "+f"(c[2]), "+f"(c[3])
        : "r"(a[0]), "r"(a[1]), "r"(a[2]), "r"(a[3]), "r"(b[0]), "r"(b[1]));
}

// ---------------------------------------------------------------------------
// Quantize-dequantize (verified R5): one division pair per block, reciprocal
// multiplies in the shrink search.
// ---------------------------------------------------------------------------
__global__ __launch_bounds__(256)
void quant_kernel(const float* __restrict__ w, __half* __restrict__ wq,
                  int nblocks) {
    int b = blockIdx.x * 8 + (threadIdx.x >> 5);
    int lane = threadIdx.x & 31;
    if (b >= nblocks) return;
    const float* p = w + (size_t)b * 64;
    float w0 = p[lane];
    float w1 = p[lane + 32];

    float amax = fmaxf(fabsf(w0), fabsf(w1));
    #pragma unroll
    for (int o = 16; o; o >>= 1) amax = fmaxf(amax, __shfl_xor_sync(0xffffffffu, amax, o));

    float am = fmaxf(amax, 1e-8f);
    float base = __fdiv_rn(am, 15.0f);
    float invb = __fdiv_rn(15.0f, am);

    const float shr[16] = {0.4f, 0.44f, 0.48f, 0.52f, 0.56f, 0.6f, 0.64f, 0.68f,
                           0.72f, 0.76f, 0.8f, 0.84f, 0.88f, 0.92f, 0.96f, 1.0f};
    const float ishr[16] = {2.5f, 1.0f/0.44f, 1.0f/0.48f, 1.0f/0.52f,
                            1.0f/0.56f, 1.0f/0.6f, 1.0f/0.64f, 1.0f/0.68f,
                            1.0f/0.72f, 1.0f/0.76f, 1.25f, 1.0f/0.84f,
                            1.0f/0.88f, 1.0f/0.92f, 1.0f/0.96f, 1.0f};
    float best_err = __int_as_float(0x7f800000);
    float best_scale = base;
    float best_inv = invb;
    #pragma unroll
    for (int i = 0; i < 16; i++) {
        float s = base * shr[i];
        float inv = invb * ishr[i];
        float q0 = fminf(fmaxf(rintf(w0 * inv), -15.f), 15.f);
        float q1 = fminf(fmaxf(rintf(w1 * inv), -15.f), 15.f);
        float d0 = fmaf(q0, s, -w0);
        float d1 = fmaf(q1, s, -w1);
        float e = fmaf(d0, d0, d1 * d1);
        #pragma unroll
        for (int o = 16; o; o >>= 1) e += __shfl_xor_sync(0xffffffffu, e, o);
        if (e < best_err) { best_err = e; best_scale = s; best_inv = inv; }
    }
    float q0 = fminf(fmaxf(rintf(w0 * best_inv), -15.f), 15.f);
    float q1 = fminf(fmaxf(rintf(w1 * best_inv), -15.f), 15.f);
    wq[(size_t)b * 64 + lane]      = __float2half_rn(q0 * best_scale);
    wq[(size_t)b * 64 + lane + 32] = __float2half_rn(q1 * best_scale);
}

__global__ void half_kernel(const float* __restrict__ in, __half* __restrict__ out, int n4) {
    int i = blockIdx.x * blockDim.x + threadIdx.x;
    int stride = gridDim.x * blockDim.x;
    for (; i < n4; i += stride) {
        float4 v = reinterpret_cast<const float4*>(in)[i];
        __half2 h0 = __floats2half2_rn(v.x, v.y);
        __half2 h1 = __floats2half2_rn(v.z, v.w);
        uint2 pk;
        pk.x = *reinterpret_cast<uint32_t*>(&h0);
        pk.y = *reinterpret_cast<uint32_t*>(&h1);
        reinterpret_cast<uint2*>(out)[i] = pk;
    }
}

// ---------------------------------------------------------------------------
// TN GEMM: C[M,N] = A[M,K] @ B[N,K]^T, fp16 in, fp32 accum.
// 128 threads, 4 warps 2x2, 64x64 warp tile, 3 stages, K/N compile-time.
// Requires (K/BKH) % 3 == 2 (true for K=2048 -> 32, K=8192 -> 128).
// ---------------------------------------------------------------------------
template <int K, int NN, bool RELUSQ>
__global__ __launch_bounds__(128, 2)
void gemm_h(const __half* __restrict__ A, const __half* __restrict__ B,
            void* __restrict__ Cv) {
    extern __shared__ char smem[];
    const uint32_t sb = (uint32_t)__cvta_generic_to_shared(smem);

    const int tid = threadIdx.x;
    const int lane = tid & 31;
    const int warp = tid >> 5;
    const int wm = warp >> 1;
    const int wn = warp & 1;
    const int bm = blockIdx.y;
    const int bn = blockIdx.x;

    // ---- loader geometry (verified R5 mapping) ----
    const int lrow = tid >> 3;
    const int lc = tid & 7;
    const uint32_t lswz = (uint32_t)((lc ^ (lrow & 7)) << 4);
    const __half* aP = A + (size_t)(bm * BM + lrow) * K + lc * 8;
    const __half* bP = B + (size_t)(bn * BN + lrow) * K + lc * 8;
    const uint32_t lsm = lrow * 128 + lswz;

    // load tile into stage at stg_off, sources ag/bg (row lrow, chunk lc)
    auto load_stage = [&](uint32_t stg_off, const __half* ag, const __half* bg) {
        uint32_t as = sb + stg_off + lsm;
        uint32_t bs = as + STAGE_A;
        #pragma unroll
        for (int i = 0; i < 8; i++)
            cp16(as + i * (16 * 128), ag + i * (16 * K));
        #pragma unroll
        for (int i = 0; i < 8; i++)
            cp16(bs + i * (16 * 128), bg + i * (16 * K));
        cp_commit();
    };

    // ---- ldmatrix per-lane geometry (verified) ----
    const int trow = lane & 7;
    const int tile = lane >> 3;
    const int t01 = tile & 1;
    const int t2 = tile >> 1;
    const uint32_t Aboff = (uint32_t)((wm * 64 + t01 * 8 + trow) * 128);
    const uint32_t Bboff = (uint32_t)(STAGE_A + (wn * 64 + t01 * 8 + trow) * 128);
    // per-lane swizzle constants for kk = 0..3
    uint32_t swz[4];
    #pragma unroll
    for (int kk = 0; kk < 4; kk++)
        swz[kk] = (uint32_t)((((2 * kk + t2) ^ trow)) << 4);

    float c[4][8][4];
    #pragma unroll
    for (int mi = 0; mi < 4; mi++)
        #pragma unroll
        for (int ni = 0; ni < 8; ni++)
            #pragma unroll
            for (int r = 0; r < 4; r++) c[mi][ni][r] = 0.f;

    constexpr int KT = K / BKH;
    static_assert(KT % 3 == 2, "tail assumes KT mod 3 == 2");

    uint32_t fa[2][4][4];
    uint32_t fb[2][8][2];

    auto loadfrag = [&](int buf, uint32_t stgA, uint32_t stgB, uint32_t sz) {
        #pragma unroll
        for (int mi = 0; mi < 4; mi++)
            ldsm4(fa[buf][mi][0], fa[buf][mi][1], fa[buf][mi][2], fa[buf][mi][3],
                  stgA + mi * 2048 + sz);
        #pragma unroll
        for (int nb = 0; nb < 4; nb++) {
            uint32_t r0, r1, r2, r3;
            ldsm4(r0, r1, r2, r3, stgB + nb * 2048 + sz);
            fb[buf][2 * nb][0] = r0; fb[buf][2 * nb][1] = r2;
            fb[buf][2 * nb + 1][0] = r1; fb[buf][2 * nb + 1][1] = r3;
        }
    };
    auto mmablock = [&](int buf) {
        #pragma unroll
        for (int mi = 0; mi < 4; mi++)
            #pragma unroll
            for (int ni = 0; ni < 8; ni++)
                mma16(c[mi][ni], fa[buf][mi], fb[buf][ni]);
    };

    // prologue: stages 0,1 <- tiles 0,1
    load_stage(0, aP, bP);
    load_stage(STAGE_BYTES, aP + BKH, bP + BKH);
    const __half* apre = aP + 2 * BKH;   // src for tile kt+2
    const __half* bpre = bP + 2 * BKH;

    // one step: consume stage at stg_off; optionally preload the tile two
    // ahead into nxt_off. last=true waits for all outstanding groups.
    auto step = [&](uint32_t stg_off, uint32_t nxt_off, bool preload, bool last) {
        if (last) cp_wait<0>(); else cp_wait<1>();
        __syncthreads();
        const uint32_t stgA = sb + stg_off + Aboff;
        const uint32_t stgB = sb + stg_off + Bboff;
        loadfrag(0, stgA, stgB, swz[0]);
        if (preload) {
            load_stage(nxt_off, apre, bpre);
            apre += BKH; bpre += BKH;
        }
        loadfrag(1, stgA, stgB, swz[1]);
        mmablock(0);
        loadfrag(0, stgA, stgB, swz[2]);
        mmablock(1);
        loadfrag(1, stgA, stgB, swz[3]);
        mmablock(0);
        mmablock(1);
    };

    constexpr uint32_t S0 = 0, S1 = STAGE_BYTES, S2 = 2 * STAGE_BYTES;
    int kt = 0;
    #pragma unroll 1
    for (; kt + 3 <= KT - 2; kt += 3) {
        step(S0, S2, true, false);
        step(S1, S0, true, false);
        step(S2, S1, true, false);
    }
    // tail: exactly 2 tiles (stages 0,1), no preload
    step(S0, S2, false, false);
    step(S1, S0, false, true);

    // ---- epilogue ----
    const int g = lane >> 2;
    const int q = lane & 3;
    const int row0 = bm * BM + wm * 64 + g;
    const int col0 = bn * BN + wn * 64 + q * 2;

    if (RELUSQ) {
        __half* C = (__half*)Cv;
        #pragma unroll
        for (int mi = 0; mi < 4; mi++) {
            #pragma unroll
            for (int ni = 0; ni < 8; ni++) {
                float v0 = fmaxf(c[mi][ni][0], 0.f); v0 *= v0;
                float v1 = fmaxf(c[mi][ni][1], 0.f); v1 *= v1;
                float v2 = fmaxf(c[mi][ni][2], 0.f); v2 *= v2;
                float v3 = fmaxf(c[mi][ni][3], 0.f); v3 *= v3;
                int r = row0 + mi * 16;
                int cc = col0 + ni * 8;
                *reinterpret_cast<__half2*>(C + (size_t)r * NN + cc) = __floats2half2_rn(v0, v1);
                *reinterpret_cast<__half2*>(C + (size_t)(r + 8) * NN + cc) = __floats2half2_rn(v2, v3);
            }
        }
    } else {
        float* C = (float*)Cv;
        #pragma unroll
        for (int mi = 0; mi < 4; mi++) {
            #pragma unroll
            for (int ni = 0; ni < 8; ni++) {
                int r = row0 + mi * 16;
                int cc = col0 + ni * 8;
                *reinterpret_cast<float2*>(C + (size_t)r * NN + cc) =
                    make_float2(c[mi][ni][0], c[mi][ni][1]);
                *reinterpret_cast<float2*>(C + (size_t)(r + 8) * NN + cc) =
                    make_float2(c[mi][ni][2], c[mi][ni][3]);
            }
        }
    }
}

// ---------------------------------------------------------------------------

extern "C" void kernel_launch(void* const* d_in, const int* in_sizes, int n_in,
                              void* d_out, int out_size) {
    const float* x     = (const float*)d_in[0];   // [8192, 2048]
    const float* wfc   = (const float*)d_in[1];   // [8192, 2048]
    const float* wproj = (const float*)d_in[2];   // [2048, 8192]
    float* out = (float*)d_out;                    // [8192, 2048]

    __half *xh, *wfcq, *wpjq, *h2;
    cudaGetSymbolAddress((void**)&xh, g_xh);
    cudaGetSymbolAddress((void**)&wfcq, g_wfc);
    cudaGetSymbolAddress((void**)&wpjq, g_wpj);
    cudaGetSymbolAddress((void**)&h2, g_h2);

    const int M = 8192, K1 = 2048, N1 = 8192, K2 = 8192, N2 = 2048;

    // typed locals for the attribute calls (host-compiler-safe)
    void (*g1)(const __half*, const __half*, void*) = gemm_h<2048, 8192, true>;
    void (*g2)(const __half*, const __half*, void*) = gemm_h<8192, 2048, false>;
    cudaFuncSetAttribute(g1, cudaFuncAttributeMaxDynamicSharedMemorySize, SMEM_TOTAL);
    cudaFuncSetAttribute(g2, cudaFuncAttributeMaxDynamicSharedMemorySize, SMEM_TOTAL);

    // 1. quantize-dequantize weights -> fp16
    {
        int nb_fc = (N1 * K1) / 64;
        quant_kernel<<<nb_fc / 8, 256>>>(wfc, wfcq, nb_fc);
        int nb_pj = (N2 * K2) / 64;
        quant_kernel<<<nb_pj / 8, 256>>>(wproj, wpjq, nb_pj);
    }

    // 2. x -> fp16
    half_kernel<<<2048, 256>>>(x, xh, (M * K1) / 4);

    // 3. h2 = half(relu(x @ wfcq^T)^2)
    {
        dim3 grid(N1 / BN, M / BM);   // (64, 64)
        gemm_h<2048, 8192, true><<<grid, 128, SMEM_TOTAL>>>(xh, wfcq, (void*)h2);
    }

    // 4. out = h2 @ wpjq^T   (fp32 out)
    {
        dim3 grid(N2 / BN, M / BM);   // (16, 64)
        gemm_h<8192, 2048, false><<<grid, 128, SMEM_TOTAL>>>(h2, wpjq, (void*)out);
    }
}